// round 9
// baseline (speedup 1.0000x reference)
#include <cuda_runtime.h>
#include <cuda_fp16.h>
#include <mma.h>
#include <cstdint>

using namespace nvcuda;

#define BB 2
#define CC 128
#define NN 10000
#define KK 16

// ---- gemm config: one full wave (140 CTAs on 148 SMs) ----
#define TMG 144
#define NTG ((NN + TMG - 1) / TMG)   // 70
#define GT 288                       // 9 warps
#define LDN 152   // xh leading dim (halfs)
#define LDW 136   // ws leading dim (halfs)
#define LDD 140   // D leading dim (floats)
#define XH_BYTES (CC * LDN * 2)          // 38912
#define WS_BYTES (CC * LDW * 2)          // 34816
#define DYN_SMEM (TMG * LDD * 4)         // 80640 > XH+WS=73728

// Scratch (static device arrays are allowed)
__device__ __align__(16) __half g_whh[BB * NN * CC];  // node-major [b][n][c] fp16
__device__ float g_s1[BB * NN];
__device__ float g_s2[BB * NN];

extern __shared__ char dyn_smem[];

// ---------------------------------------------------------------------------
// Kernel 1: WMMA GEMM, fp16 in / fp32 accum. Tile 144n x 128o, K=128.
// Grid (70, 2) = 140 CTAs -> exactly one wave. 9 warps, warp = 16n x 128o.
// (unchanged from round 8 — measured ~9.6us, HMMA/staging bound)
// ---------------------------------------------------------------------------
__global__ void __launch_bounds__(GT) gemm_wmma(const float* __restrict__ x,
                                                const float* __restrict__ W,
                                                const float* __restrict__ a) {
    __shared__ float a_s[2 * CC];
    __shared__ float s_part[2][2][TMG];

    half*  xh = (half*)dyn_smem;                 // [CC][LDN]
    half*  ws = (half*)(dyn_smem + XH_BYTES);    // [CC][LDW]
    float* D  = (float*)dyn_smem;                // phase 2: [TMG][LDD]

    int tid = threadIdx.x;
    int b = blockIdx.y;
    int n0 = blockIdx.x * TMG;

    if (tid < 2 * CC) a_s[tid] = a[tid];

    // Stage x tile -> xh[c][n] fp16 (9216 float2 loads, 32/thread, full unroll)
#pragma unroll
    for (int it = 0; it < 32; it++) {
        int idx = it * GT + tid;
        int c = idx / 72;
        int n2 = idx - c * 72;
        int n = n0 + n2 * 2;
        const float* xp = &x[((size_t)b * CC + c) * NN + n];
        float f0 = (n < NN) ? xp[0] : 0.f;
        float f1 = (n + 1 < NN) ? xp[1] : 0.f;
        *(half2*)&xh[c * LDN + n2 * 2] = __floats2half2_rn(f0, f1);
    }
    // Stage W -> ws[o][c] fp16 (8192 float2, 29 guarded iters)
#pragma unroll
    for (int it = 0; it < 29; it++) {
        int idx = it * GT + tid;
        if (idx < 8192) {
            int o = idx >> 6;
            int c2 = idx & 63;
            float2 wv = *(const float2*)&W[o * CC + c2 * 2];
            *(half2*)&ws[o * LDW + c2 * 2] = __floats2half2_rn(wv.x, wv.y);
        }
    }
    __syncthreads();

    int w = tid >> 5;   // 0..8, rows [w*16, +16)

    wmma::fragment<wmma::accumulator, 16, 16, 16, float> acc[8];
#pragma unroll
    for (int j = 0; j < 8; j++) wmma::fill_fragment(acc[j], 0.f);

#pragma unroll
    for (int k = 0; k < 8; k++) {
        wmma::fragment<wmma::matrix_a, 16, 16, 16, half, wmma::col_major> af;
        wmma::load_matrix_sync(af, xh + (k * 16) * LDN + w * 16, LDN);
#pragma unroll
        for (int j = 0; j < 8; j++) {
            wmma::fragment<wmma::matrix_b, 16, 16, 16, half, wmma::col_major> bf;
            wmma::load_matrix_sync(bf, ws + (j * 16) * LDW + k * 16, LDW);
            wmma::mma_sync(acc[j], af, bf, acc[j]);
        }
    }
    __syncthreads();   // all input reads done before D overwrites buffer

#pragma unroll
    for (int j = 0; j < 8; j++)
        wmma::store_matrix_sync(D + (w * 16) * LDD + j * 16, acc[j], LDD,
                                wmma::mem_row_major);
    __syncthreads();

    // Epilogue: thread -> (node nd, o-half hf)
    {
        int hf = tid / TMG;          // 0/1
        int nd = tid - hf * TMG;
        int n = n0 + nd;
        const float* row = D + nd * LDD + hf * 64;
        float s1 = 0.f, s2 = 0.f;
        half2 hrow[32];
#pragma unroll
        for (int q = 0; q < 16; q++) {
            float4 v = *(const float4*)&row[q * 4];
            int o = hf * 64 + q * 4;
            s1 += a_s[o] * v.x + a_s[o + 1] * v.y + a_s[o + 2] * v.z + a_s[o + 3] * v.w;
            s2 += a_s[CC + o] * v.x + a_s[CC + o + 1] * v.y
                + a_s[CC + o + 2] * v.z + a_s[CC + o + 3] * v.w;
            hrow[q * 2]     = __floats2half2_rn(v.x, v.y);
            hrow[q * 2 + 1] = __floats2half2_rn(v.z, v.w);
        }
        s_part[hf][0][nd] = s1;
        s_part[hf][1][nd] = s2;
        if (n < NN) {
            uint4* dst = (uint4*)&g_whh[((size_t)b * NN + n) * CC + hf * 64];
#pragma unroll
            for (int q = 0; q < 8; q++) dst[q] = ((uint4*)hrow)[q];
        }
    }
    __syncthreads();

    // Combine s partials
    {
        int which = tid / TMG;
        int nd = tid - which * TMG;
        int n = n0 + nd;
        if (n < NN) {
            float s = s_part[0][which][nd] + s_part[1][which][nd];
            if (which) g_s2[b * NN + n] = s;
            else       g_s1[b * NN + n] = s;
        }
    }
}

// ---------------------------------------------------------------------------
// Kernel 2: attention + aggregation. Two nodes per warp. (A, j) parked in a
// per-node smem table after softmax (warp-private -> __syncwarp only), so the
// gather loop's addresses come from broadcast LDS issued 4-deep ahead instead
// of serialized SHFL chains.
// ---------------------------------------------------------------------------
__global__ void __launch_bounds__(256) gat_kernel(const int* __restrict__ ei,
                                                  float* __restrict__ out) {
    __shared__ float hs[16 * 132];   // [node_local][c], padded
    __shared__ float As[16][16];     // [node_local][k]
    __shared__ int   Js[16][16];

    int tid = threadIdx.x;   // 256
    int lane = tid & 31;
    int w = tid >> 5;        // 0..7
    int b = blockIdx.y;
    int n0 = blockIdx.x * 16;          // grid.x = 625
    int nh = lane >> 4;                // node half 0/1
    int nl = 2 * w + nh;               // node local 0..15
    int n = n0 + nl;
    int kk = lane & 15;

    int j = ei[(((size_t)0 * BB + b) * NN + n) * KK + kk];
    int i = ei[(((size_t)1 * BB + b) * NN + n) * KK + kk];

    float e = g_s1[b * NN + i] + g_s2[b * NN + j];
    e = (e > 0.f) ? e : 0.2f * e;

    // softmax within each 16-lane half
    float em = e;
#pragma unroll
    for (int m = 8; m; m >>= 1) em = fmaxf(em, __shfl_xor_sync(0xffffffffu, em, m));
    float p = __expf(e - em);
    float ps = p;
#pragma unroll
    for (int m = 8; m; m >>= 1) ps += __shfl_xor_sync(0xffffffffu, ps, m);

    As[nl][kk] = p / ps;
    Js[nl][kk] = j;
    __syncwarp();

    // gather: lane owns channels [kk*8, kk*8+8) of its node (uint4 = 16B fp16)
    const uint4* whb = (const uint4*)g_whh + (size_t)b * NN * 16;
    float acc[8];
#pragma unroll
    for (int q = 0; q < 8; q++) acc[q] = 0.f;

#pragma unroll
    for (int batch = 0; batch < 4; batch++) {
        int jk[4];
#pragma unroll
        for (int t = 0; t < 4; t++) jk[t] = Js[nl][batch * 4 + t];   // LDS bcast
        uint4 v[4];
#pragma unroll
        for (int t = 0; t < 4; t++) v[t] = whb[(size_t)jk[t] * 16 + kk];
        float Ak[4];
#pragma unroll
        for (int t = 0; t < 4; t++) Ak[t] = As[nl][batch * 4 + t];   // LDS bcast
#pragma unroll
        for (int t = 0; t < 4; t++) {
            const __half2* h = (const __half2*)&v[t];
#pragma unroll
            for (int q = 0; q < 4; q++) {
                float2 f = __half22float2(h[q]);
                acc[2 * q]     += Ak[t] * f.x;
                acc[2 * q + 1] += Ak[t] * f.y;
            }
        }
    }

    *(float4*)&hs[nl * 132 + kk * 8]     = *(float4*)&acc[0];
    *(float4*)&hs[nl * 132 + kk * 8 + 4] = *(float4*)&acc[4];
    __syncthreads();

    // transposed coalesced write: out[b][c][n0..n0+16)
#pragma unroll
    for (int r = 0; r < 8; r++) {
        int c = (tid >> 4) + r * 16;
        int nn = tid & 15;
        out[((size_t)b * CC + c) * NN + n0 + nn] = hs[nn * 132 + c];
    }
}

// ---------------------------------------------------------------------------
extern "C" void kernel_launch(void* const* d_in, const int* in_sizes, int n_in,
                              void* d_out, int out_size) {
    const float* x = (const float*)d_in[0];       // [B,C,N,1]
    const int* ei  = (const int*)d_in[1];         // [2,B,N,K]
    const float* W = (const float*)d_in[2];       // [C,C]
    const float* a = (const float*)d_in[3];       // [2C]
    float* out     = (float*)d_out;               // [B,C,N,1]

    cudaFuncSetAttribute(gemm_wmma, cudaFuncAttributeMaxDynamicSharedMemorySize,
                         DYN_SMEM);
    gemm_wmma<<<dim3(NTG, BB), GT, DYN_SMEM>>>(x, W, a);
    gat_kernel<<<dim3(NN / 16, BB), 256>>>(ei, out);
}